// round 17
// baseline (speedup 1.0000x reference)
#include <cuda_runtime.h>

#define KSZ   2
#define CIN   3
#define COUT  16
#define HIN   256
#define WIN   256
#define HF    255
#define WF    255
#define HO    254
#define WO    254
#define BATCH 64
#define NPIX  (BATCH * HF * WF)
#define BN_EPS 1e-5f

#define NTAP  12
#define NF    45            // [0..2]=P, [3..8]=F00(tri), [9..17]=F01, [18..26]=F1m1, [27..35]=F10, [36..44]=F11
#define NBND  132           // 4 edges x 21 + 4 corners x 12
#define CSTR  13            // per-channel constant stride: 12 scaled weights + shift
#define TPBASE 124          // thin region: pair-columns 124..127

typedef unsigned long long u64;

__device__ __forceinline__ u64 pk2(float lo, float hi) {
    u64 r; asm("mov.b64 %0,{%1,%2};" : "=l"(r) : "f"(lo), "f"(hi)); return r;
}
__device__ __forceinline__ void up2(u64 v, float& lo, float& hi) {
    asm("mov.b64 {%0,%1},%2;" : "=f"(lo), "=f"(hi) : "l"(v));
}
__device__ __forceinline__ u64 fma2(u64 a, u64 b, u64 c) {
    u64 d; asm("fma.rn.f32x2 %0,%1,%2,%3;" : "=l"(d) : "l"(a), "l"(b), "l"(c)); return d;
}
__device__ __forceinline__ u64 mul2(u64 a, u64 b) {
    u64 d; asm("mul.rn.f32x2 %0,%1,%2;" : "=l"(d) : "l"(a), "l"(b)); return d;
}
__device__ __forceinline__ u64 add2(u64 a, u64 b) {
    u64 d; asm("add.rn.f32x2 %0,%1,%2;" : "=l"(d) : "l"(a), "l"(b)); return d;
}
__device__ __forceinline__ float tha(float x) {
    float y; asm("tanh.approx.f32 %0,%1;" : "=f"(y) : "f"(x)); return y;
}

__constant__ u64 c_all[COUT * CSTR];

__device__ double g_stat[NF];    // correlations (rows 0..254) + P (rows 0..254, all cols)
__device__ double g_bnd[NBND];   // boundary strips + corners
__device__ u64    g_all[COUT * CSTR];

// ---------------------------------------------------------------------------
// Kernel 1a: full-plane correlations, rows 0..254. Thread = col pair.
// Per pixel: P (3 adds) + 42 correlation FMAs. Zero-filled edge taps make
// out-of-range products vanish automatically.
// ---------------------------------------------------------------------------
__global__ void __launch_bounds__(256, 2) stats_kernel(const float* __restrict__ x) {
    float P[3], F00[6], F01[9], F1m[9], F10[9], F11[9];
#pragma unroll
    for (int i = 0; i < 3; i++) P[i] = 0.f;
#pragma unroll
    for (int i = 0; i < 6; i++) F00[i] = 0.f;
#pragma unroll
    for (int i = 0; i < 9; i++) { F01[i]=0.f; F1m[i]=0.f; F10[i]=0.f; F11[i]=0.f; }

    const int p  = threadIdx.x & 127;          // pair 0..127 -> cols 2p, 2p+1
    const int s  = threadIdx.x >> 7;           // strip 0/1
    const int j  = 2 * p;
    const int i0 = blockIdx.x * 64 + s * 32;
    const int nr = (255 - i0 < 32) ? (255 - i0) : 32;   // pixel rows i0..i0+nr-1 (<=254)
    const float* xb = x + (size_t)blockIdx.y * CIN * HIN * WIN;
    const bool pl = (p > 0), pr_ok = (p < 127);

    float cur[CIN][3], nxt[CIN][4], pf[CIN][4];
#pragma unroll
    for (int c = 0; c < CIN; c++) {
        const float* q = xb + (size_t)c * HIN * WIN + (size_t)i0 * WIN + j;
        float2 a = *(const float2*)q;
        cur[c][0] = a.x; cur[c][1] = a.y;
        cur[c][2] = pr_ok ? __ldg(q + 2) : 0.f;
        nxt[c][0] = pl ? __ldg(q + WIN - 1) : 0.f;
        float2 b = *(const float2*)(q + WIN);
        nxt[c][1] = b.x; nxt[c][2] = b.y;
        nxt[c][3] = pr_ok ? __ldg(q + WIN + 2) : 0.f;
    }

    for (int r = 0; r < nr; r++) {
        int prw = i0 + r + 2; if (prw > 255) prw = 255;
#pragma unroll
        for (int c = 0; c < CIN; c++) {
            const float* q = xb + (size_t)c * HIN * WIN + (size_t)prw * WIN + j;
            pf[c][0] = pl ? __ldg(q - 1) : 0.f;
            float2 a = *(const float2*)q;
            pf[c][1] = a.x; pf[c][2] = a.y;
            pf[c][3] = pr_ok ? __ldg(q + 2) : 0.f;
        }

#pragma unroll
        for (int c = 0; c < CIN; c++) P[c] += cur[c][0] + cur[c][1];
        // F00 (triangular a<=b)
        {
            int t = 0;
#pragma unroll
            for (int a = 0; a < 3; a++)
#pragma unroll
                for (int b = a; b < 3; b++, t++) {
                    F00[t] = fmaf(cur[a][0], cur[b][0], F00[t]);
                    F00[t] = fmaf(cur[a][1], cur[b][1], F00[t]);
                }
        }
#pragma unroll
        for (int a = 0; a < 3; a++)
#pragma unroll
            for (int b = 0; b < 3; b++) {
                const int t = a * 3 + b;
                F01[t] = fmaf(cur[a][0], cur[b][1], F01[t]);
                F01[t] = fmaf(cur[a][1], cur[b][2], F01[t]);
                F1m[t] = fmaf(cur[a][0], nxt[b][0], F1m[t]);
                F1m[t] = fmaf(cur[a][1], nxt[b][1], F1m[t]);
                F10[t] = fmaf(cur[a][0], nxt[b][1], F10[t]);
                F10[t] = fmaf(cur[a][1], nxt[b][2], F10[t]);
                F11[t] = fmaf(cur[a][0], nxt[b][2], F11[t]);
                F11[t] = fmaf(cur[a][1], nxt[b][3], F11[t]);
            }
#pragma unroll
        for (int c = 0; c < CIN; c++) {
            cur[c][0] = nxt[c][1]; cur[c][1] = nxt[c][2]; cur[c][2] = nxt[c][3];
            nxt[c][0] = pf[c][0]; nxt[c][1] = pf[c][1];
            nxt[c][2] = pf[c][2]; nxt[c][3] = pf[c][3];
        }
    }

    // pack into 45-slot vector and reduce
    float acc[NF];
#pragma unroll
    for (int i = 0; i < 3; i++) acc[i] = P[i];
#pragma unroll
    for (int i = 0; i < 6; i++) acc[3 + i] = F00[i];
#pragma unroll
    for (int i = 0; i < 9; i++) {
        acc[9 + i] = F01[i]; acc[18 + i] = F1m[i];
        acc[27 + i] = F10[i]; acc[36 + i] = F11[i];
    }
    const unsigned m = 0xffffffffu;
#pragma unroll
    for (int k = 0; k < NF; k++) {
        float a = acc[k];
#pragma unroll
        for (int o = 16; o > 0; o >>= 1) a += __shfl_xor_sync(m, a, o);
        acc[k] = a;
    }
    __shared__ float red[8][NF];
    const int warp = threadIdx.x >> 5, lane = threadIdx.x & 31;
    if (lane == 0) {
#pragma unroll
        for (int k = 0; k < NF; k++) red[warp][k] = acc[k];
    }
    __syncthreads();
    if (threadIdx.x < NF) {
        float tot = 0.f;
#pragma unroll
        for (int w = 0; w < 8; w++) tot += red[w][threadIdx.x];
        atomicAdd(&g_stat[threadIdx.x], (double)tot);
    }
}

// ---------------------------------------------------------------------------
// Kernel 1b: boundary strips + corners. 1 block per image, warp per strip.
// Edge e: 0=row0, 1=row255, 2=col0, 3=col255. Per edge 21 sums:
// m<9: v_a(t)v_b(t); m<18: v_a(t)v_b(t+1) (t<255); else v_a(t).
// ---------------------------------------------------------------------------
__global__ void __launch_bounds__(256) boundary_kernel(const float* __restrict__ x) {
    const float* xb = x + (size_t)blockIdx.x * CIN * HIN * WIN;
    const int warp = threadIdx.x >> 5, lane = threadIdx.x & 31;
    const unsigned msk = 0xffffffffu;

    for (int sidx = warp; sidx < 84; sidx += 8) {
        const int e = sidx / 21, mm = sidx % 21;
        float sum = 0.f;
        for (int t = lane; t < 256; t += 32) {
            // v_c(t) and v_c(t+1) along edge e
            auto V = [&](int c, int tt) -> float {
                if (e == 0) return xb[(size_t)c * HIN * WIN + tt];
                if (e == 1) return xb[(size_t)c * HIN * WIN + 255 * WIN + tt];
                if (e == 2) return xb[(size_t)c * HIN * WIN + (size_t)tt * WIN];
                return xb[(size_t)c * HIN * WIN + (size_t)tt * WIN + 255];
            };
            if (mm < 9) {
                sum += V(mm / 3, t) * V(mm % 3, t);
            } else if (mm < 18) {
                if (t < 255) sum += V((mm - 9) / 3, t) * V((mm - 9) % 3, t + 1);
            } else {
                sum += V(mm - 18, t);
            }
        }
#pragma unroll
        for (int o = 16; o > 0; o >>= 1) sum += __shfl_xor_sync(msk, sum, o);
        if (lane == 0) atomicAdd(&g_bnd[sidx], (double)sum);
    }

    // corners: c = (ri?2:0)+(cj?1:0); 12 values each
    if (threadIdx.x < 48) {
        const int c = threadIdx.x / 12, mm = threadIdx.x % 12;
        const int ri = (c >> 1) ? 255 : 0, cj = (c & 1) ? 255 : 0;
        auto X = [&](int ch) -> float {
            return xb[(size_t)ch * HIN * WIN + (size_t)ri * WIN + cj];
        };
        float val = (mm < 9) ? X(mm / 3) * X(mm % 3) : X(mm - 9);
        atomicAdd(&g_bnd[84 + c * 12 + mm], (double)val);
    }
}

// ---------------------------------------------------------------------------
// Kernel 2: reconstruct S[12]/G[78] from correlations + boundaries (fp64),
// re-zero accumulators, fold BN into packed scaled weights + shift.
// ---------------------------------------------------------------------------
__device__ __forceinline__ int fidx(int u, int v, int a, int b) {
    if (u == 0 && v == 0) return 3 + a * 3 - a * (a + 1) / 2 + b;  // tri, a<=b
    if (u == 0) return 9 + a * 3 + b;          // v==1
    if (v == -1) return 18 + a * 3 + b;
    if (v == 0)  return 27 + a * 3 + b;
    return 36 + a * 3 + b;                     // v==1
}

__global__ void finalize_kernel(const float* __restrict__ w,
                                const float* __restrict__ gamma,
                                const float* __restrict__ beta) {
    __shared__ double sF[NF], sB[NBND], sS[NTAP], sG[78];
    const int t = threadIdx.x;
    if (t < NF)  sF[t] = g_stat[t];
    if (t < NBND) sB[t] = g_bnd[t];
    __syncthreads();
    if (t < NF)  g_stat[t] = 0.0;
    if (t < NBND) g_bnd[t] = 0.0;

    // helpers into sB
    auto RowB = [&](int ri, int v, int a, int b) -> double {
        return sB[(ri ? 21 : 0) + (v ? 9 + a * 3 + b : a * 3 + b)];
    };
    auto ColB = [&](int cj, int u, int a, int b) -> double {
        return sB[(cj ? 63 : 42) + (u ? 9 + a * 3 + b : a * 3 + b)];
    };
    auto CornB = [&](int ri, int cj, int a, int b) -> double {
        return sB[84 + ((ri ? 2 : 0) + (cj ? 1 : 0)) * 12 + a * 3 + b];
    };

    if (t < 78) {
        // decode triangular (k,l), l<=k
        int k = 0;
        while ((k + 1) * (k + 2) / 2 <= t) k++;
        const int l = t - k * (k + 1) / 2;
        int a1 = k / 4, dy1 = (k >> 1) & 1, dx1 = k & 1;
        int a2 = l / 4, dy2 = (l >> 1) & 1, dx2 = l & 1;
        int u = dy2 - dy1, v = dx2 - dx1;
        if (u < 0 || (u == 0 && v < 0) || (u == 0 && v == 0 && a1 > a2)) {
            int tmp;
            tmp = a1; a1 = a2; a2 = tmp;
            dy1 = dy2; dx1 = dx2;
            u = -u; v = -v;
        }
        double F = sF[fidx(u, v, a1, a2)];
        if (u == 0) F += RowB(255, v, a1, a2);   // complete (0,*) sums to rows [0,255]
        const int ri = (dy1 == 0) ? 255 : 0;
        const int cj = (dx1 == 0) ? 255 : 0;
        double corr = 0.0;
        if (u == 0) corr += RowB(ri, v, a1, a2);
        if (v == 0) corr += ColB(cj, u, a1, a2);
        if (u == 0 && v == 0) corr -= CornB(ri, cj, a1, a2);
        sG[t] = F - corr;
    }
    if (t >= 78 && t < 78 + NTAP) {
        const int k = t - 78;
        const int a = k / 4, dy = (k >> 1) & 1, dx = k & 1;
        const int ri = (dy == 0) ? 255 : 0;
        const int cj = (dx == 0) ? 255 : 0;
        double Pf = sF[a] + sB[21 + 18 + a];     // + row 255 single sum
        Pf -= sB[(ri ? 21 : 0) + 18 + a];
        Pf -= sB[(cj ? 63 : 42) + 18 + a];
        Pf += sB[84 + ((ri ? 2 : 0) + (cj ? 1 : 0)) * 12 + 9 + a];
        sS[k] = Pf;
    }
    __syncthreads();

    if (t >= COUT) return;
    const int c = t;
    const double N = (double)NPIX;
    double wc[NTAP];
#pragma unroll
    for (int k = 0; k < NTAP; k++) wc[k] = (double)w[c * NTAP + k];

    double mean = 0.0;
#pragma unroll
    for (int k = 0; k < NTAP; k++) mean += wc[k] * sS[k];
    mean /= N;

    double e2 = 0.0;
#pragma unroll
    for (int k = 0; k < NTAP; k++) {
#pragma unroll
        for (int l = 0; l <= k; l++) {
            double g = sG[k * (k + 1) / 2 + l];
            double tt = wc[k] * wc[l] * g;
            e2 += (l == k) ? tt : 2.0 * tt;
        }
    }
    e2 /= N;
    double var = e2 - mean * mean;
    float scale = gamma[c] * rsqrtf((float)var + BN_EPS);
    float shift = beta[c] - (float)mean * scale;
#pragma unroll
    for (int k = 0; k < NTAP; k++) {
        float ws = w[c * NTAP + k] * scale;
        g_all[c * CSTR + k] = pk2(ws, ws);
    }
    g_all[c * CSTR + NTAP] = pk2(shift, shift);
}

// ---------------------------------------------------------------------------
// fused conv+BN+relu+tanh+window core (R15 — proven)
// ---------------------------------------------------------------------------
__device__ __forceinline__ void conv_core(const u64 e[CIN][3], const u64 o[CIN][3],
                                          float accA[2], float accB[2]) {
#pragma unroll 1
    for (int c = 0; c < COUT; c++) {
        const u64* w = &c_all[c * CSTR];
        const u64 sh = w[NTAP];
#pragma unroll
        for (int i = 0; i < 2; i++) {
            u64 v0 = fma2(w[0], e[0][i], sh);
            v0 = fma2(w[1],  o[0][i],     v0);
            v0 = fma2(w[2],  e[0][i + 1], v0);
            v0 = fma2(w[3],  o[0][i + 1], v0);
            v0 = fma2(w[4],  e[1][i],     v0);
            v0 = fma2(w[5],  o[1][i],     v0);
            u64 v1 = mul2(w[6], e[1][i + 1]);
            v1 = fma2(w[7],  o[1][i + 1], v1);
            v1 = fma2(w[8],  e[2][i],     v1);
            v1 = fma2(w[9],  o[2][i],     v1);
            v1 = fma2(w[10], e[2][i + 1], v1);
            v1 = fma2(w[11], o[2][i + 1], v1);
            u64 v = add2(v0, v1);
            float lo, hi; up2(v, lo, hi);
            accA[i] += tha(fmaxf(lo, 0.f));
            accB[i] += tha(fmaxf(hi, 0.f));
        }
    }
}

__global__ void __launch_bounds__(256, 4) fused_out_kernel(const float* __restrict__ x,
                                                           float* __restrict__ out) {
    __shared__ union {
        struct { u64 pe[CIN][17][33]; u64 st[16][33]; } m;
        struct { u64 pe[CIN][129][5]; u64 st[128][4]; } t;
    } sm;

    const int tid = threadIdx.x;
    const int b   = blockIdx.z;
    const float* xb = x + (size_t)b * CIN * HIN * WIN;
    const float inv = 1.0f / (COUT * KSZ * KSZ);

    if (blockIdx.y < 17) {
        const int oy0 = blockIdx.y * 15;
        const int ox0 = blockIdx.x * 62;

        for (int idx = tid; idx < CIN * 17 * 33; idx += 256) {
            const int jc = idx % 33;
            const int t2 = idx / 33;
            const int r  = t2 % 17;
            const int ci = t2 / 17;
            const int gr = oy0 + r, gc = ox0 + 2 * jc;
            u64 v = 0ull;
            if (gr < HIN && gc < WIN)
                v = *(const u64*)&xb[(size_t)(ci * HIN + gr) * WIN + gc];
            sm.m.pe[ci][r][jc] = v;
        }
        __syncthreads();

        const int jp = tid & 31;
        const int r0 = (tid >> 5) * 2;

        u64 e[CIN][3], o[CIN][3];
#pragma unroll
        for (int ci = 0; ci < CIN; ci++) {
#pragma unroll
            for (int i = 0; i < 3; i++) {
                u64 ev = sm.m.pe[ci][r0 + i][jp];
                u64 en = sm.m.pe[ci][r0 + i][jp + 1];
                float elo, ehi, nlo, nhi;
                up2(ev, elo, ehi); up2(en, nlo, nhi);
                e[ci][i] = ev;
                o[ci][i] = pk2(ehi, nlo);
            }
        }

        float accA[2] = {0.f, 0.f}, accB[2] = {0.f, 0.f};
        conv_core(e, o, accA, accB);
        sm.m.st[r0 + 0][jp] = pk2(accA[0], accB[0]);
        sm.m.st[r0 + 1][jp] = pk2(accA[1], accB[1]);
        __syncthreads();

        const float* stf = (const float*)sm.m.st;
        for (int p = tid; p < 62 * 15; p += 256) {
            const int oy = p / 62, ox_ = p - oy * 62;
            const int oi = oy0 + oy, oj = ox0 + ox_;
            if (oi < HO) {
                const float* rp = stf + oy * 66 + ox_;
                out[(size_t)(b * HO + oi) * WO + oj] =
                    (rp[0] + rp[1] + rp[66] + rp[67]) * inv;
            }
        }
    } else {
        if (blockIdx.x != 0) return;
        const int oy0 = (blockIdx.y == 17) ? 0 : 127;

        for (int idx = tid; idx < CIN * 129 * 5; idx += 256) {
            const int jc = idx % 5;
            const int t2 = idx / 5;
            const int r  = t2 % 129;
            const int ci = t2 / 129;
            const int gr = oy0 + r, gc = 2 * (TPBASE + jc);
            u64 v = 0ull;
            if (gr < HIN && gc < WIN)
                v = *(const u64*)&xb[(size_t)(ci * HIN + gr) * WIN + gc];
            sm.t.pe[ci][r][jc] = v;
        }
        __syncthreads();

        const int jp = tid & 3;
        const int r0 = (tid >> 2) * 2;

        u64 e[CIN][3], o[CIN][3];
#pragma unroll
        for (int ci = 0; ci < CIN; ci++) {
#pragma unroll
            for (int i = 0; i < 3; i++) {
                u64 ev = sm.t.pe[ci][r0 + i][jp];
                u64 en = sm.t.pe[ci][r0 + i][jp + 1];
                float elo, ehi, nlo, nhi;
                up2(ev, elo, ehi); up2(en, nlo, nhi);
                e[ci][i] = ev;
                o[ci][i] = pk2(ehi, nlo);
            }
        }

        float accA[2] = {0.f, 0.f}, accB[2] = {0.f, 0.f};
        conv_core(e, o, accA, accB);
        sm.t.st[r0 + 0][jp] = pk2(accA[0], accB[0]);
        sm.t.st[r0 + 1][jp] = pk2(accA[1], accB[1]);
        __syncthreads();

        const float* stf = (const float*)sm.t.st;
        for (int p = tid; p < 6 * 127; p += 256) {
            const int ly = p / 6, ox_ = p - ly * 6;
            const int oi = oy0 + ly, oj = 2 * TPBASE + ox_;
            const float* rp = stf + ly * 8 + ox_;
            out[(size_t)(b * HO + oi) * WO + oj] =
                (rp[0] + rp[1] + rp[8] + rp[9]) * inv;
        }
    }
}

// ---------------------------------------------------------------------------
// kernel_launch: inputs: x, conv_w, conv_b (cancels under BN), gamma, beta
// ---------------------------------------------------------------------------
extern "C" void kernel_launch(void* const* d_in, const int* in_sizes, int n_in,
                              void* d_out, int out_size) {
    const float* x      = (const float*)d_in[0];
    const float* conv_w = (const float*)d_in[1];
    const float* gamma  = (const float*)d_in[3];
    const float* beta   = (const float*)d_in[4];
    float* out = (float*)d_out;

    void* p_all = 0;
    cudaGetSymbolAddress(&p_all, g_all);

    boundary_kernel<<<BATCH, 256>>>(x);
    dim3 sgrid(4, BATCH);                       // 4 x 64 = 256 blocks, one wave
    stats_kernel<<<sgrid, 256>>>(x);
    finalize_kernel<<<1, 160>>>(conv_w, gamma, beta);
    cudaMemcpyToSymbolAsync(c_all, p_all, COUT * CSTR * sizeof(u64),
                            0, cudaMemcpyDeviceToDevice, 0);

    dim3 grid(4, 19, BATCH);   // y<17: main 62x15 tiles; y in {17,18}: thin tile
    fused_out_kernel<<<grid, 256>>>(x, out);
}